// round 11
// baseline (speedup 1.0000x reference)
#include <cuda_runtime.h>
#include <math.h>
#include <stdint.h>

#define B  8
#define C  64
#define Hc 256
#define Wc 256
#define CR 128
#define HR 128
#define WR 128

__device__ float g_scores[B * CR];
__device__ int   g_idx[B * C];
__device__ int   g_done[B];
__device__ int   g_tdone[B];

__global__ void init_kernel() {
    int t = threadIdx.x;
    if (t < B) { g_done[t] = 0; g_tdone[t] = 0; }
}

// ---------------------------------------------------------------------------
// Persistent mega-kernel: scores -> topk -> fuse, one launch, 1024 CTAs
// (all co-resident; forward-only dependencies via L2 atomics).
// CTA bid: scores plane bid; if (bid%128==0) topk for batch bid/128;
// then 8 fuse tiles (one per batch, batch order), tile-in-batch = bid.
// ---------------------------------------------------------------------------
__global__ void __launch_bounds__(256, 7) mega_kernel(
    const float* __restrict__ x,
    const float* __restrict__ readout,
    const float* __restrict__ weight,
    const float* __restrict__ bias,
    float* __restrict__ out)
{
    __shared__ float wA[HR];
    __shared__ float red[8];
    __shared__ float srow[10 * WR];
    __shared__ float tsv[CR];
    __shared__ int   tsi[CR];

    const int tid = threadIdx.x;
    const int bid = blockIdx.x;            // 0..1023
    const int b_s = bid >> 7;              // batch of the score plane
    const int cr  = bid & 127;
    const float cst = (float)(127.0 / 255.0);

    // ---- axis weights ----
    if (tid < HR) wA[tid] = 0.0f;
    __syncthreads();
    {
        float pos = (float)tid * cst;
        int i0 = (int)pos;
        if (i0 > HR - 2) i0 = HR - 2;
        float w = pos - (float)i0;
        atomicAdd(&wA[i0], 1.0f - w);
        atomicAdd(&wA[i0 + 1], w);
    }
    __syncthreads();

    // ======================= Phase A: score of plane bid ====================
    {
        const float4* __restrict__ src =
            (const float4*)(readout + (size_t)bid * (HR * WR));
        float acc0 = 0.f, acc1 = 0.f, acc2 = 0.f, acc3 = 0.f;
        #pragma unroll
        for (int it = 0; it < 4; it++) {
            float4 v[4];
            #pragma unroll
            for (int j = 0; j < 4; j++)
                v[j] = __ldg(&src[tid + (it * 4 + j) * 256]);
            #pragma unroll
            for (int j = 0; j < 4; j++) {
                int base = (tid + (it * 4 + j) * 256) << 2;
                int row = base >> 7;
                int col = base & 127;
                float wr = wA[row];
                float s = wA[col] * v[j].x + wA[col + 1] * v[j].y +
                          wA[col + 2] * v[j].z + wA[col + 3] * v[j].w;
                if (j == 0) acc0 += wr * s;
                else if (j == 1) acc1 += wr * s;
                else if (j == 2) acc2 += wr * s;
                else acc3 += wr * s;
            }
        }
        float acc = (acc0 + acc1) + (acc2 + acc3);
        #pragma unroll
        for (int s = 16; s > 0; s >>= 1)
            acc += __shfl_down_sync(0xffffffffu, acc, s);
        if ((tid & 31) == 0) red[tid >> 5] = acc;
        __syncthreads();
        if (tid == 0) {
            float t = 0.f;
            #pragma unroll
            for (int w2 = 0; w2 < 8; w2++) t += red[w2];
            g_scores[bid] = t * (1.0f / (float)(Hc * Wc));
            __threadfence();
            atomicAdd(&g_done[b_s], 1);
        }
    }

    // ======================= Phase B: topk (cr==0 CTAs) =====================
    if (cr == 0) {
        if (tid == 0) {
            while (atomicAdd(&g_done[b_s], 0) < CR) __nanosleep(64);
        }
        __syncthreads();
        __threadfence();
        if (tid < CR) {
            tsv[tid] = __ldcg(&g_scores[b_s * CR + tid]);
            tsi[tid] = tid;
        }
        __syncthreads();
        for (int k = 2; k <= CR; k <<= 1) {
            for (int j = k >> 1; j > 0; j >>= 1) {
                if (tid < CR) {
                    int ixj = tid ^ j;
                    if (ixj > tid) {
                        float va = tsv[tid], vb = tsv[ixj];
                        int   ia = tsi[tid], ib = tsi[ixj];
                        bool first = (va > vb) || (va == vb && ia < ib);
                        bool ascSeg = ((tid & k) == 0);
                        bool doSwap = ascSeg ? (!first) : first;
                        if (doSwap) {
                            tsv[tid] = vb; tsv[ixj] = va;
                            tsi[tid] = ib; tsi[ixj] = ia;
                        }
                    }
                }
                __syncthreads();
            }
        }
        if (tid < C) g_idx[b_s * C + tid] = tsi[tid];
        __syncthreads();
        if (tid == 0) {
            __threadfence();
            atomicExch(&g_tdone[b_s], 1);
        }
    }

    // ======================= Phase C: fuse, 8 tiles =========================
    const int c    = bid >> 4;             // 0..63
    const int yblk = bid & 15;             // 0..15
    const int y0 = yblk << 4;

    int iy_lo = (int)((float)y0 * cst);        if (iy_lo > HR - 2) iy_lo = HR - 2;
    int iy_hi = (int)((float)(y0 + 15) * cst); if (iy_hi > HR - 2) iy_hi = HR - 2;
    iy_hi += 1;
    const int nrows = iy_hi - iy_lo + 1;      // <= 10
    const int nslots = nrows * 32;

    const float w0 = __ldg(weight + 2 * c);
    const float w1 = __ldg(weight + 2 * c + 1);
    const float bs = __ldg(bias + c);

    const int tx = tid & 63;
    const int ty = tid >> 6;
    const int x0 = tx << 2;

    int   ixA[4];
    float wxA[4];
    #pragma unroll
    for (int k = 0; k < 4; k++) {
        float posx = (float)(x0 + k) * cst;
        int ix0 = (int)posx;
        if (ix0 > WR - 2) ix0 = WR - 2;
        ixA[k] = ix0;
        wxA[k] = posx - (float)ix0;
    }

    for (int j = 0; j < B; j++) {
        if (tid == 0) {
            while (atomicAdd(&g_tdone[j], 0) == 0) __nanosleep(64);
        }
        __syncthreads();

        const int plane = j * C + c;
        const int ch = __ldcg(&g_idx[plane]);
        const float* __restrict__ rsrc =
            readout + ((size_t)j * CR + ch) * (HR * WR);

        // front-batched stage loads
        float4 sv0, sv1;
        const bool st0 = (tid < nslots);
        const bool st1 = (tid + 256 < nslots);
        if (st0)
            sv0 = __ldg((const float4*)(rsrc + (iy_lo + (tid >> 5)) * WR + ((tid & 31) << 2)));
        if (st1)
            sv1 = __ldg((const float4*)(rsrc + (iy_lo + ((tid + 256) >> 5)) * WR + (((tid + 256) & 31) << 2)));

        // front-batched x loads: 4 rows, dense float4 lanes
        float4 xv[4];
        #pragma unroll
        for (int r = 0; r < 4; r++) {
            int y = y0 + ty + (r << 2);
            xv[r] = __ldcs((const float4*)(x + ((size_t)plane * Hc + y) * Wc + x0));
        }

        if (st0) *(float4*)(srow + (tid >> 5) * WR + ((tid & 31) << 2)) = sv0;
        if (st1) *(float4*)(srow + ((tid + 256) >> 5) * WR + (((tid + 256) & 31) << 2)) = sv1;
        __syncthreads();

        #pragma unroll
        for (int r = 0; r < 4; r++) {
            const int y = y0 + ty + (r << 2);
            float posy = (float)y * cst;
            int iy0 = (int)posy;
            if (iy0 > HR - 2) iy0 = HR - 2;
            const float wy = posy - (float)iy0;
            const float wy0 = 1.0f - wy;

            const float* __restrict__ s0 = srow + (iy0 - iy_lo) * WR;
            const float* __restrict__ s1 = s0 + WR;

            float xs[4] = {xv[r].x, xv[r].y, xv[r].z, xv[r].w};
            float os[4];
            #pragma unroll
            for (int k = 0; k < 4; k++) {
                int ix0 = ixA[k];
                // reference order: interpolate along H first, then W
                float a  = s0[ix0]     * wy0 + s1[ix0]     * wy;
                float bb = s0[ix0 + 1] * wy0 + s1[ix0 + 1] * wy;
                float rv = a * (1.0f - wxA[k]) + bb * wxA[k];
                float t = xs[k] * w0 + rv * w1 + bs;
                float gate = 1.0f / (1.0f + __expf(-t));
                os[k] = xs[k] + gate * (rv - xs[k]);
            }
            __stcs((float4*)(out + ((size_t)plane * Hc + y) * Wc + x0),
                   make_float4(os[0], os[1], os[2], os[3]));
        }
        __syncthreads();   // srow reuse safety for next batch
    }
}

// ---------------------------------------------------------------------------
extern "C" void kernel_launch(void* const* d_in, const int* in_sizes, int n_in,
                              void* d_out, int out_size)
{
    const float* x       = (const float*)d_in[0];
    const float* readout = (const float*)d_in[1];
    const float* weight  = (const float*)d_in[2];
    const float* bias    = (const float*)d_in[3];
    float* out = (float*)d_out;

    init_kernel<<<1, 32>>>();
    mega_kernel<<<B * CR, 256>>>(x, readout, weight, bias, out);
}

// round 12
// speedup vs baseline: 1.7503x; 1.7503x over previous
#include <cuda_runtime.h>
#include <math.h>
#include <stdint.h>

#define B  8
#define C  64
#define Hc 256
#define Wc 256
#define CR 128
#define HR 128
#define WR 128

__device__ float g_scores[B * CR];
__device__ int   g_idx[B * C];
__device__ int   g_done[B];      // zero-initialized; reset to 0 by the topk CTA

// ---------------------------------------------------------------------------
// Kernel 1: analytic upsample-mean score (proven R4 body) + INLINE topk.
// Each CTA scores one (b,cr) plane. The last CTA to finish within a batch
// performs the 128-wide descending bitonic sort (tie: lower index first,
// matching jax.lax.top_k) and writes g_idx, then resets the batch counter.
// ---------------------------------------------------------------------------
__global__ void __launch_bounds__(256) scores_kernel(const float* __restrict__ readout) {
    __shared__ float wA[HR];
    __shared__ float red[8];
    __shared__ float tsv[CR];
    __shared__ int   tsi[CR];
    __shared__ int   s_last;

    const int tid = threadIdx.x;
    const int plane = blockIdx.x;          // b*CR + cr
    const int b = plane >> 7;

    if (tid < HR) wA[tid] = 0.0f;
    __syncthreads();
    {
        const float cst = (float)(127.0 / 255.0);
        float pos = (float)tid * cst;
        int i0 = (int)pos;
        if (i0 > HR - 2) i0 = HR - 2;
        float w = pos - (float)i0;
        atomicAdd(&wA[i0], 1.0f - w);
        atomicAdd(&wA[i0 + 1], w);
    }
    __syncthreads();

    const float4* __restrict__ src =
        (const float4*)(readout + (size_t)plane * (HR * WR));

    float acc0 = 0.f, acc1 = 0.f, acc2 = 0.f, acc3 = 0.f;
    #pragma unroll
    for (int half = 0; half < 2; half++) {
        float4 v[8];
        #pragma unroll
        for (int j = 0; j < 8; j++)
            v[j] = src[tid + (half * 8 + j) * 256];
        #pragma unroll
        for (int j = 0; j < 8; j++) {
            int base = (tid + (half * 8 + j) * 256) << 2;
            int row = base >> 7;
            int col = base & 127;
            float wr = wA[row];
            float s = wA[col] * v[j].x + wA[col + 1] * v[j].y +
                      wA[col + 2] * v[j].z + wA[col + 3] * v[j].w;
            if (j == 0 || j == 4) acc0 += wr * s;
            else if (j == 1 || j == 5) acc1 += wr * s;
            else if (j == 2 || j == 6) acc2 += wr * s;
            else acc3 += wr * s;
        }
    }

    float acc = (acc0 + acc1) + (acc2 + acc3);
    #pragma unroll
    for (int s = 16; s > 0; s >>= 1)
        acc += __shfl_down_sync(0xffffffffu, acc, s);
    if ((tid & 31) == 0) red[tid >> 5] = acc;
    __syncthreads();

    if (tid == 0) {
        float t = 0.f;
        #pragma unroll
        for (int w2 = 0; w2 < 8; w2++) t += red[w2];
        g_scores[plane] = t * (1.0f / (float)(Hc * Wc));
        __threadfence();
        int old = atomicAdd(&g_done[b], 1);
        s_last = (old == CR - 1) ? 1 : 0;
    }
    __syncthreads();

    if (!s_last) return;

    // ---- this CTA finished last in its batch: do topk inline ----
    __threadfence();   // acquire all g_scores of this batch
    if (tid < CR) {
        tsv[tid] = __ldcg(&g_scores[b * CR + tid]);
        tsi[tid] = tid;
    }
    __syncthreads();

    for (int k = 2; k <= CR; k <<= 1) {
        for (int j = k >> 1; j > 0; j >>= 1) {
            if (tid < CR) {
                int ixj = tid ^ j;
                if (ixj > tid) {
                    float va = tsv[tid], vb = tsv[ixj];
                    int   ia = tsi[tid], ib = tsi[ixj];
                    bool first = (va > vb) || (va == vb && ia < ib);
                    bool ascSeg = ((tid & k) == 0);
                    bool doSwap = ascSeg ? (!first) : first;
                    if (doSwap) {
                        tsv[tid] = vb; tsv[ixj] = va;
                        tsi[tid] = ib; tsi[ixj] = ia;
                    }
                }
            }
            __syncthreads();
        }
    }

    if (tid < C) g_idx[b * C + tid] = tsi[tid];
    if (tid == 0) g_done[b] = 0;    // reset for next graph replay (deterministic)
}

// ---------------------------------------------------------------------------
// Kernel 2: fused bilinear-upsample + gated blend (proven R4 body).
// Block = 16 output rows x 256 cols (256 threads). All global loads
// front-batched before the single barrier; streamed float4 stores.
// ---------------------------------------------------------------------------
__global__ void __launch_bounds__(256) fuse_kernel(
    const float* __restrict__ x,
    const float* __restrict__ readout,
    const float* __restrict__ weight,
    const float* __restrict__ bias,
    float* __restrict__ out)
{
    __shared__ float srow[10 * WR];

    const int plane = blockIdx.z;
    const int b = plane >> 6;
    const int c = plane & (C - 1);
    const int ch = g_idx[plane];

    const float* __restrict__ rsrc =
        readout + ((size_t)b * CR + ch) * (HR * WR);

    const int y0 = blockIdx.y << 4;          // 16 rows per block
    const float cst = (float)(127.0 / 255.0);

    int iy_lo = (int)((float)y0 * cst);        if (iy_lo > HR - 2) iy_lo = HR - 2;
    int iy_hi = (int)((float)(y0 + 15) * cst); if (iy_hi > HR - 2) iy_hi = HR - 2;
    iy_hi += 1;
    const int nrows = iy_hi - iy_lo + 1;      // <= 10

    const int tid = threadIdx.x;

    // ---- front-batched stage loads (up to 320 slots over 256 threads) ----
    const int nslots = nrows * 32;
    float4 sv0, sv1;
    const bool st0 = (tid < nslots);
    const bool st1 = (tid + 256 < nslots);
    if (st0)
        sv0 = __ldg((const float4*)(rsrc + (iy_lo + (tid >> 5)) * WR + ((tid & 31) << 2)));
    if (st1)
        sv1 = __ldg((const float4*)(rsrc + (iy_lo + ((tid + 256) >> 5)) * WR + (((tid + 256) & 31) << 2)));

    // ---- front-batched x loads: 4 rows, dense float4 lanes ----
    const int tx = tid & 63;
    const int ty = tid >> 6;
    const int x0 = tx << 2;

    size_t o[4];
    float4 xv[4];
    #pragma unroll
    for (int r = 0; r < 4; r++) {
        int y = y0 + ty + (r << 2);
        o[r] = ((size_t)plane * Hc + y) * Wc + x0;
        xv[r] = __ldcs((const float4*)(x + o[r]));
    }

    if (st0) *(float4*)(srow + (tid >> 5) * WR + ((tid & 31) << 2)) = sv0;
    if (st1) *(float4*)(srow + ((tid + 256) >> 5) * WR + (((tid + 256) & 31) << 2)) = sv1;
    __syncthreads();

    const float w0 = __ldg(weight + 2 * c);
    const float w1 = __ldg(weight + 2 * c + 1);
    const float bs = __ldg(bias + c);

    int   ixA[4];
    float wxA[4];
    #pragma unroll
    for (int k = 0; k < 4; k++) {
        float posx = (float)(x0 + k) * cst;
        int ix0 = (int)posx;
        if (ix0 > WR - 2) ix0 = WR - 2;
        ixA[k] = ix0;
        wxA[k] = posx - (float)ix0;
    }

    #pragma unroll
    for (int r = 0; r < 4; r++) {
        const int y = y0 + ty + (r << 2);
        float posy = (float)y * cst;
        int iy0 = (int)posy;
        if (iy0 > HR - 2) iy0 = HR - 2;
        const float wy = posy - (float)iy0;
        const float wy0 = 1.0f - wy;

        const float* __restrict__ s0 = srow + (iy0 - iy_lo) * WR;
        const float* __restrict__ s1 = s0 + WR;

        float xs[4] = {xv[r].x, xv[r].y, xv[r].z, xv[r].w};
        float os[4];
        #pragma unroll
        for (int k = 0; k < 4; k++) {
            int ix0 = ixA[k];
            // reference order: interpolate along H first, then W
            float a  = s0[ix0]     * wy0 + s1[ix0]     * wy;
            float bb = s0[ix0 + 1] * wy0 + s1[ix0 + 1] * wy;
            float rv = a * (1.0f - wxA[k]) + bb * wxA[k];
            float t = xs[k] * w0 + rv * w1 + bs;
            float gate = 1.0f / (1.0f + __expf(-t));
            os[k] = xs[k] + gate * (rv - xs[k]);
        }
        __stcs((float4*)(out + o[r]), make_float4(os[0], os[1], os[2], os[3]));
    }
}

// ---------------------------------------------------------------------------
extern "C" void kernel_launch(void* const* d_in, const int* in_sizes, int n_in,
                              void* d_out, int out_size)
{
    const float* x       = (const float*)d_in[0];
    const float* readout = (const float*)d_in[1];
    const float* weight  = (const float*)d_in[2];
    const float* bias    = (const float*)d_in[3];
    float* out = (float*)d_out;

    scores_kernel<<<B * CR, 256>>>(readout);

    dim3 blk(256, 1, 1);
    dim3 grd(1, Hc / 16, B * C);   // 8192 blocks
    fuse_kernel<<<grd, blk>>>(x, readout, weight, bias, out);
}

// round 13
// speedup vs baseline: 2.0322x; 1.1610x over previous
#include <cuda_runtime.h>
#include <math.h>
#include <stdint.h>

#define B  8
#define C  64
#define Hc 256
#define Wc 256
#define CR 128
#define HR 128
#define WR 128

__device__ float g_scores[B * CR];
__device__ int   g_idx[B * C];
__device__ int   g_done[B];      // zero-init; reset by the topk CTA each call

// ---------------------------------------------------------------------------
// Kernel 1: analytic upsample-mean score + inline topk (proven R12 version).
// ---------------------------------------------------------------------------
__global__ void __launch_bounds__(256) scores_kernel(const float* __restrict__ readout) {
    __shared__ float wA[HR];
    __shared__ float red[8];
    __shared__ float tsv[CR];
    __shared__ int   tsi[CR];
    __shared__ int   s_last;

    const int tid = threadIdx.x;
    const int plane = blockIdx.x;          // b*CR + cr
    const int b = plane >> 7;

    if (tid < HR) wA[tid] = 0.0f;
    __syncthreads();
    {
        const float cst = (float)(127.0 / 255.0);
        float pos = (float)tid * cst;
        int i0 = (int)pos;
        if (i0 > HR - 2) i0 = HR - 2;
        float w = pos - (float)i0;
        atomicAdd(&wA[i0], 1.0f - w);
        atomicAdd(&wA[i0 + 1], w);
    }
    __syncthreads();

    const float4* __restrict__ src =
        (const float4*)(readout + (size_t)plane * (HR * WR));

    float acc0 = 0.f, acc1 = 0.f, acc2 = 0.f, acc3 = 0.f;
    #pragma unroll
    for (int half = 0; half < 2; half++) {
        float4 v[8];
        #pragma unroll
        for (int j = 0; j < 8; j++)
            v[j] = src[tid + (half * 8 + j) * 256];
        #pragma unroll
        for (int j = 0; j < 8; j++) {
            int base = (tid + (half * 8 + j) * 256) << 2;
            int row = base >> 7;
            int col = base & 127;
            float wr = wA[row];
            float s = wA[col] * v[j].x + wA[col + 1] * v[j].y +
                      wA[col + 2] * v[j].z + wA[col + 3] * v[j].w;
            if (j == 0 || j == 4) acc0 += wr * s;
            else if (j == 1 || j == 5) acc1 += wr * s;
            else if (j == 2 || j == 6) acc2 += wr * s;
            else acc3 += wr * s;
        }
    }

    float acc = (acc0 + acc1) + (acc2 + acc3);
    #pragma unroll
    for (int s = 16; s > 0; s >>= 1)
        acc += __shfl_down_sync(0xffffffffu, acc, s);
    if ((tid & 31) == 0) red[tid >> 5] = acc;
    __syncthreads();

    if (tid == 0) {
        float t = 0.f;
        #pragma unroll
        for (int w2 = 0; w2 < 8; w2++) t += red[w2];
        g_scores[plane] = t * (1.0f / (float)(Hc * Wc));
        __threadfence();
        int old = atomicAdd(&g_done[b], 1);
        s_last = (old == CR - 1) ? 1 : 0;
    }
    __syncthreads();

    if (!s_last) return;

    __threadfence();
    if (tid < CR) {
        tsv[tid] = __ldcg(&g_scores[b * CR + tid]);
        tsi[tid] = tid;
    }
    __syncthreads();

    for (int k = 2; k <= CR; k <<= 1) {
        for (int j = k >> 1; j > 0; j >>= 1) {
            if (tid < CR) {
                int ixj = tid ^ j;
                if (ixj > tid) {
                    float va = tsv[tid], vb = tsv[ixj];
                    int   ia = tsi[tid], ib = tsi[ixj];
                    bool first = (va > vb) || (va == vb && ia < ib);
                    bool ascSeg = ((tid & k) == 0);
                    bool doSwap = ascSeg ? (!first) : first;
                    if (doSwap) {
                        tsv[tid] = vb; tsv[ixj] = va;
                        tsi[tid] = ib; tsi[ixj] = ia;
                    }
                }
            }
            __syncthreads();
        }
    }

    if (tid < C) g_idx[b * C + tid] = tsi[tid];
    if (tid == 0) g_done[b] = 0;
}

// ---------------------------------------------------------------------------
// Kernel 2: fused 2x-upsample + gated blend, STATIC-STENCIL form.
// out[2m]   = src[m-1]*(m/255)       + src[m]*(1-m/255)
// out[2m+1] = src[m]*(1-(127-m)/255) + src[m+1]*((127-m)/255)
// All tap indices/weights static per thread. Readout rows staged in an
// even/odd-split smem layout -> all 8 LDS per row are stride-1 conflict-free.
// ---------------------------------------------------------------------------
__global__ void __launch_bounds__(256) fuse_kernel(
    const float* __restrict__ x,
    const float* __restrict__ readout,
    const float* __restrict__ weight,
    const float* __restrict__ bias,
    float* __restrict__ out)
{
    __shared__ float srow2[10 * 128];   // [row][0..63]=even cols, [64..127]=odd

    const int plane = blockIdx.z;
    const int b = plane >> 6;
    const int c = plane & (C - 1);
    const int ch = g_idx[plane];

    const float* __restrict__ rsrc =
        readout + ((size_t)b * CR + ch) * (HR * WR);

    const int y0 = blockIdx.y << 4;           // 16 output rows per block
    const int n0 = y0 >> 1;
    const int iy_lo = (n0 - 1 > 0) ? n0 - 1 : 0;
    const int iy_hi = (n0 + 8 < HR - 1) ? n0 + 8 : HR - 1;
    const int nrows = iy_hi - iy_lo + 1;      // 9..10

    const int tid = threadIdx.x;

    // ---- front-batched stage loads (nrows*32 slots over 256 threads) ----
    const int nslots = nrows * 32;
    float4 sv0, sv1;
    const bool st0 = (tid < nslots);
    const bool st1 = (tid + 256 < nslots);
    if (st0)
        sv0 = __ldg((const float4*)(rsrc + (iy_lo + (tid >> 5)) * WR + ((tid & 31) << 2)));
    if (st1)
        sv1 = __ldg((const float4*)(rsrc + (iy_lo + ((tid + 256) >> 5)) * WR + (((tid + 256) & 31) << 2)));

    // ---- front-batched x loads: 4 rows, dense float4 lanes ----
    const int tx = tid & 63;
    const int ty = tid >> 6;
    const int x0 = tx << 2;

    size_t o[4];
    float4 xv[4];
    #pragma unroll
    for (int r = 0; r < 4; r++) {
        int y = y0 + ty + (r << 2);
        o[r] = ((size_t)plane * Hc + y) * Wc + x0;
        xv[r] = __ldcs((const float4*)(x + o[r]));
    }

    // deswizzled stage writes: even cols -> [0..63], odd cols -> [64..127]
    if (st0) {
        float* base = srow2 + (tid >> 5) * 128;
        int q = tid & 31;
        ((float2*)base)[q]        = make_float2(sv0.x, sv0.z);
        ((float2*)(base + 64))[q] = make_float2(sv0.y, sv0.w);
    }
    if (st1) {
        float* base = srow2 + ((tid + 256) >> 5) * 128;
        int q = (tid + 256) & 31;
        ((float2*)base)[q]        = make_float2(sv1.x, sv1.z);
        ((float2*)(base + 64))[q] = make_float2(sv1.y, sv1.w);
    }
    __syncthreads();

    const float w0c = __ldg(weight + 2 * c);
    const float w1c = __ldg(weight + 2 * c + 1);
    const float bsc = __ldg(bias + c);

    // ---- static horizontal constants (per thread) ----
    const float inv255 = 1.0f / 255.0f;
    const float m0 = (float)(2 * tx);
    const float w0h = 1.0f - m0 * inv255;            // on c1 for px0
    const float w1h = (127.0f - m0) * inv255;        // on c2 for px1
    const float w2h = 1.0f - (m0 + 1.0f) * inv255;   // on c2 for px2
    const float w3h = (126.0f - m0) * inv255;        // on c3 for px3
    const int txm = (tx > 0) ? tx - 1 : 0;
    const int txp = (tx < 63) ? tx + 1 : 63;

    #pragma unroll
    for (int r = 0; r < 4; r++) {
        const int y = y0 + ty + (r << 2);
        const int n = y >> 1;
        const int p = y & 1;
        // vertical taps: even y -> rows (n-1, n), w_hi = 1 - n/255
        //                odd  y -> rows (n, n+1), w_hi = (127-n)/255
        int rl = p ? n : ((n - 1 > 0) ? n - 1 : 0);
        int rh = p ? ((n + 1 < HR - 1) ? n + 1 : HR - 1) : n;
        float wv = p ? (127.0f - (float)n) * inv255
                     : 1.0f - (float)n * inv255;

        const float* __restrict__ L = srow2 + (rl - iy_lo) * 128;
        const float* __restrict__ H = srow2 + (rh - iy_lo) * 128;

        // 8 conflict-free LDS + 4 vertical lerps
        float c1 = fmaf(wv, H[tx]        - L[tx],        L[tx]);         // src[2tx]
        float c3 = fmaf(wv, H[txp]       - L[txp],       L[txp]);        // src[2tx+2]
        float c0 = fmaf(wv, H[64 + txm]  - L[64 + txm],  L[64 + txm]);   // src[2tx-1]
        float c2 = fmaf(wv, H[64 + tx]   - L[64 + tx],   L[64 + tx]);    // src[2tx+1]

        // 4 static horizontal lerps
        float rv0 = fmaf(w0h, c1 - c0, c0);
        float rv1 = fmaf(w1h, c2 - c1, c1);
        float rv2 = fmaf(w2h, c2 - c1, c1);
        float rv3 = fmaf(w3h, c3 - c2, c2);

        float xs[4] = {xv[r].x, xv[r].y, xv[r].z, xv[r].w};
        float rvv[4] = {rv0, rv1, rv2, rv3};
        float os[4];
        #pragma unroll
        for (int k = 0; k < 4; k++) {
            float t = fmaf(xs[k], w0c, fmaf(rvv[k], w1c, bsc));
            float gate = __fdividef(1.0f, 1.0f + __expf(-t));
            os[k] = fmaf(gate, rvv[k] - xs[k], xs[k]);
        }
        __stcs((float4*)(out + o[r]), make_float4(os[0], os[1], os[2], os[3]));
    }
}

// ---------------------------------------------------------------------------
extern "C" void kernel_launch(void* const* d_in, const int* in_sizes, int n_in,
                              void* d_out, int out_size)
{
    const float* x       = (const float*)d_in[0];
    const float* readout = (const float*)d_in[1];
    const float* weight  = (const float*)d_in[2];
    const float* bias    = (const float*)d_in[3];
    float* out = (float*)d_out;

    scores_kernel<<<B * CR, 256>>>(readout);

    dim3 blk(256, 1, 1);
    dim3 grd(1, Hc / 16, B * C);   // 8192 blocks
    fuse_kernel<<<grd, blk>>>(x, readout, weight, bias, out);
}

// round 14
// speedup vs baseline: 2.0868x; 1.0269x over previous
#include <cuda_runtime.h>
#include <math.h>
#include <stdint.h>

#define B  8
#define C  64
#define Hc 256
#define Wc 256
#define CR 128
#define HR 128
#define WR 128

__device__ float g_scores[B * CR];
__device__ int   g_idx[B * C];
__device__ int   g_done[B];      // zero-init; reset by the topk CTA each call

// ---------------------------------------------------------------------------
// Kernel 1: analytic upsample-mean score + inline topk (proven R12 version).
// ---------------------------------------------------------------------------
__global__ void __launch_bounds__(256) scores_kernel(const float* __restrict__ readout) {
    __shared__ float wA[HR];
    __shared__ float red[8];
    __shared__ float tsv[CR];
    __shared__ int   tsi[CR];
    __shared__ int   s_last;

    const int tid = threadIdx.x;
    const int plane = blockIdx.x;          // b*CR + cr
    const int b = plane >> 7;

    if (tid < HR) wA[tid] = 0.0f;
    __syncthreads();
    {
        const float cst = (float)(127.0 / 255.0);
        float pos = (float)tid * cst;
        int i0 = (int)pos;
        if (i0 > HR - 2) i0 = HR - 2;
        float w = pos - (float)i0;
        atomicAdd(&wA[i0], 1.0f - w);
        atomicAdd(&wA[i0 + 1], w);
    }
    __syncthreads();

    const float4* __restrict__ src =
        (const float4*)(readout + (size_t)plane * (HR * WR));

    float acc0 = 0.f, acc1 = 0.f, acc2 = 0.f, acc3 = 0.f;
    #pragma unroll
    for (int half = 0; half < 2; half++) {
        float4 v[8];
        #pragma unroll
        for (int j = 0; j < 8; j++)
            v[j] = src[tid + (half * 8 + j) * 256];
        #pragma unroll
        for (int j = 0; j < 8; j++) {
            int base = (tid + (half * 8 + j) * 256) << 2;
            int row = base >> 7;
            int col = base & 127;
            float wr = wA[row];
            float s = wA[col] * v[j].x + wA[col + 1] * v[j].y +
                      wA[col + 2] * v[j].z + wA[col + 3] * v[j].w;
            if (j == 0 || j == 4) acc0 += wr * s;
            else if (j == 1 || j == 5) acc1 += wr * s;
            else if (j == 2 || j == 6) acc2 += wr * s;
            else acc3 += wr * s;
        }
    }

    float acc = (acc0 + acc1) + (acc2 + acc3);
    #pragma unroll
    for (int s = 16; s > 0; s >>= 1)
        acc += __shfl_down_sync(0xffffffffu, acc, s);
    if ((tid & 31) == 0) red[tid >> 5] = acc;
    __syncthreads();

    if (tid == 0) {
        float t = 0.f;
        #pragma unroll
        for (int w2 = 0; w2 < 8; w2++) t += red[w2];
        g_scores[plane] = t * (1.0f / (float)(Hc * Wc));
        __threadfence();
        int old = atomicAdd(&g_done[b], 1);
        s_last = (old == CR - 1) ? 1 : 0;
    }
    __syncthreads();

    if (!s_last) return;

    __threadfence();
    if (tid < CR) {
        tsv[tid] = __ldcg(&g_scores[b * CR + tid]);
        tsi[tid] = tid;
    }
    __syncthreads();

    for (int k = 2; k <= CR; k <<= 1) {
        for (int j = k >> 1; j > 0; j >>= 1) {
            if (tid < CR) {
                int ixj = tid ^ j;
                if (ixj > tid) {
                    float va = tsv[tid], vb = tsv[ixj];
                    int   ia = tsi[tid], ib = tsi[ixj];
                    bool first = (va > vb) || (va == vb && ia < ib);
                    bool ascSeg = ((tid & k) == 0);
                    bool doSwap = ascSeg ? (!first) : first;
                    if (doSwap) {
                        tsv[tid] = vb; tsv[ixj] = va;
                        tsi[tid] = ib; tsi[ixj] = ia;
                    }
                }
            }
            __syncthreads();
        }
    }

    if (tid < C) g_idx[b * C + tid] = tsi[tid];
    if (tid == 0) g_done[b] = 0;
}

// ---------------------------------------------------------------------------
// Kernel 2: fused 2x-upsample + gated blend. Static stencil + row-pair reuse:
// each thread handles 4 CONSECUTIVE output rows, which need only src rows
// {n-1, n, n+1, n+2}; per column 4 LDS serve all 4 rows (16 LDS/thread).
// Even/odd-split smem layout keeps all LDS stride-1 conflict-free.
// ---------------------------------------------------------------------------
__global__ void __launch_bounds__(256) fuse_kernel(
    const float* __restrict__ x,
    const float* __restrict__ readout,
    const float* __restrict__ weight,
    const float* __restrict__ bias,
    float* __restrict__ out)
{
    __shared__ float srow2[10 * 128];   // [row][0..63]=even cols, [64..127]=odd

    const int plane = blockIdx.z;
    const int b = plane >> 6;
    const int c = plane & (C - 1);
    const int ch = g_idx[plane];

    const float* __restrict__ rsrc =
        readout + ((size_t)b * CR + ch) * (HR * WR);

    const int y0 = blockIdx.y << 4;           // 16 output rows per block
    const int n0 = y0 >> 1;
    const int iy_lo = (n0 - 1 > 0) ? n0 - 1 : 0;
    const int iy_hi = (n0 + 8 < HR - 1) ? n0 + 8 : HR - 1;
    const int nrows = iy_hi - iy_lo + 1;      // 9..10

    const int tid = threadIdx.x;

    // ---- front-batched stage loads (nrows*32 slots over 256 threads) ----
    const int nslots = nrows * 32;
    float4 sv0, sv1;
    const bool st0 = (tid < nslots);
    const bool st1 = (tid + 256 < nslots);
    if (st0)
        sv0 = __ldg((const float4*)(rsrc + (iy_lo + (tid >> 5)) * WR + ((tid & 31) << 2)));
    if (st1)
        sv1 = __ldg((const float4*)(rsrc + (iy_lo + ((tid + 256) >> 5)) * WR + (((tid + 256) & 31) << 2)));

    // ---- front-batched x loads: 4 CONSECUTIVE rows, dense float4 lanes ----
    const int tx = tid & 63;
    const int ty = tid >> 6;
    const int x0 = tx << 2;
    const int yb = y0 + (ty << 2);            // this thread's first output row

    size_t o0 = ((size_t)plane * Hc + yb) * Wc + x0;
    float4 xv[4];
    #pragma unroll
    for (int r = 0; r < 4; r++)
        xv[r] = __ldcs((const float4*)(x + o0 + (size_t)r * Wc));

    // deswizzled stage writes: even cols -> [0..63], odd cols -> [64..127]
    if (st0) {
        float* base = srow2 + (tid >> 5) * 128;
        int q = tid & 31;
        ((float2*)base)[q]        = make_float2(sv0.x, sv0.z);
        ((float2*)(base + 64))[q] = make_float2(sv0.y, sv0.w);
    }
    if (st1) {
        float* base = srow2 + ((tid + 256) >> 5) * 128;
        int q = (tid + 256) & 31;
        ((float2*)base)[q]        = make_float2(sv1.x, sv1.z);
        ((float2*)(base + 64))[q] = make_float2(sv1.y, sv1.w);
    }
    __syncthreads();

    const float w0c = __ldg(weight + 2 * c);
    const float w1c = __ldg(weight + 2 * c + 1);
    const float bsc = __ldg(bias + c);

    // ---- static horizontal constants (per thread) ----
    const float inv255 = 1.0f / 255.0f;
    const float m0 = (float)(2 * tx);
    const float w0h = 1.0f - m0 * inv255;            // on c1 for px0
    const float w1h = (127.0f - m0) * inv255;        // on c2 for px1
    const float w2h = 1.0f - (m0 + 1.0f) * inv255;   // on c2 for px2
    const float w3h = (126.0f - m0) * inv255;        // on c3 for px3
    const int txm = (tx > 0) ? tx - 1 : 0;
    const int txp = (tx < 63) ? tx + 1 : 63;

    // ---- vertical structure: rows yb..yb+3 need src rows n-1, n, n+1, n+2 --
    const int n = yb >> 1;
    const float fn = (float)n;
    const float w_e0 = 1.0f - fn * inv255;            // row yb   (even, L=n-1,H=n)
    const float w_o0 = (127.0f - fn) * inv255;        // row yb+1 (odd,  L=n,  H=n+1)
    const float w_e1 = 1.0f - (fn + 1.0f) * inv255;   // row yb+2 (even, L=n,  H=n+1)
    const float w_o1 = (126.0f - fn) * inv255;        // row yb+3 (odd,  L=n+1,H=n+2)

    int rA = n - 1; if (rA < 0) rA = 0;
    int rD = n + 2; if (rD > HR - 1) rD = HR - 1;
    const float* __restrict__ pA = srow2 + (rA    - iy_lo) * 128;
    const float* __restrict__ pB = srow2 + (n     - iy_lo) * 128;
    const float* __restrict__ pC = srow2 + (n + 1 - iy_lo) * 128;
    const float* __restrict__ pD = srow2 + (rD    - iy_lo) * 128;

    // per-column vertical values for the 4 rows: v[row][col 0..3]
    float vr[4][4];
    const int cofs[4] = {64 + txm, tx, 64 + tx, txp};   // c0, c1, c2, c3
    #pragma unroll
    for (int q = 0; q < 4; q++) {
        const int cc = cofs[q];
        float a = pA[cc], bv = pB[cc], cv = pC[cc], d = pD[cc];
        vr[0][q] = fmaf(w_e0, bv - a,  a);    // row yb
        vr[1][q] = fmaf(w_o0, cv - bv, bv);   // row yb+1
        vr[2][q] = fmaf(w_e1, cv - bv, bv);   // row yb+2
        vr[3][q] = fmaf(w_o1, d  - cv, cv);   // row yb+3
    }

    #pragma unroll
    for (int r = 0; r < 4; r++) {
        float c0 = vr[r][0], c1 = vr[r][1], c2 = vr[r][2], c3 = vr[r][3];
        float rv0 = fmaf(w0h, c1 - c0, c0);
        float rv1 = fmaf(w1h, c2 - c1, c1);
        float rv2 = fmaf(w2h, c2 - c1, c1);
        float rv3 = fmaf(w3h, c3 - c2, c2);

        float xs[4] = {xv[r].x, xv[r].y, xv[r].z, xv[r].w};
        float rvv[4] = {rv0, rv1, rv2, rv3};
        float os[4];
        #pragma unroll
        for (int k = 0; k < 4; k++) {
            float t = fmaf(xs[k], w0c, fmaf(rvv[k], w1c, bsc));
            float gate = __fdividef(1.0f, 1.0f + __expf(-t));
            os[k] = fmaf(gate, rvv[k] - xs[k], xs[k]);
        }
        __stcs((float4*)(out + o0 + (size_t)r * Wc),
               make_float4(os[0], os[1], os[2], os[3]));
    }
}

// ---------------------------------------------------------------------------
extern "C" void kernel_launch(void* const* d_in, const int* in_sizes, int n_in,
                              void* d_out, int out_size)
{
    const float* x       = (const float*)d_in[0];
    const float* readout = (const float*)d_in[1];
    const float* weight  = (const float*)d_in[2];
    const float* bias    = (const float*)d_in[3];
    float* out = (float*)d_out;

    scores_kernel<<<B * CR, 256>>>(readout);

    dim3 blk(256, 1, 1);
    dim3 grd(1, Hc / 16, B * C);   // 8192 blocks
    fuse_kernel<<<grd, blk>>>(x, readout, weight, bias, out);
}